// round 5
// baseline (speedup 1.0000x reference)
#include <cuda_runtime.h>

#define Hh   51
#define HP   64          // padded rows per gate (LG*NP)
#define KP   52          // padded cols = 13 float4 (col 51 zero)
#define NCH  13
#define Tt   2048
#define OTot 2112
#define Bt   8192
#define BPC  64          // batch elements per CTA
#define TPB  256         // (BPC/NB) groups * LG lanes
#define NB   4           // batches per thread
#define LG   16          // lanes per group
#define NP   4           // row-positions per lane (LG*NP = HP)
#define HS   64          // h stride per batch (floats)
#define GW   (HP*KP)     // floats per gate block = 3328

typedef unsigned long long u64;

__device__ __forceinline__ void fma2(u64 &d, u64 a, u64 b){
    asm("fma.rn.f32x2 %0, %1, %2, %0;" : "+l"(d) : "l"(a), "l"(b));
}
__device__ __forceinline__ float sum2(u64 v){
    float a, b;
    asm("mov.b64 {%0,%1}, %2;" : "=f"(a), "=f"(b) : "l"(v));
    return a + b;
}
__device__ __forceinline__ float sigm(float x){
    return __fdividef(1.0f, 1.0f + __expf(-x));
}
__device__ __forceinline__ float tanh_f(float x){
    float ax = fabsf(x);
    float e  = __expf(-2.0f * ax);
    float r  = __fdividef(1.0f - e, 1.0f + e);
    return copysignf(r, x);
}

// One pass over K for TWO gates (G1, G2) x NB batches x NP positions.
// Wt is pre-offset by gid*KP (this lane's base row); bt/wxt pre-offset by gid.
// All remaining offsets are compile-time constants.
template<int G1, int G2, bool WX>
__device__ __forceinline__ void gate_pass(
    const float* __restrict__ Wt,
    const float* __restrict__ bt,
    const float* __restrict__ wxt,
    const float* __restrict__ h0, const float* __restrict__ h1,
    const float* __restrict__ h2, const float* __restrict__ h3,
    const float xv[NB],
    float (&o1)[NB][NP], float (&o2)[NB][NP])
{
    u64 a1[NB][NP], a2[NB][NP];
    #pragma unroll
    for (int q = 0; q < NB; q++)
        #pragma unroll
        for (int p = 0; p < NP; p++){ a1[q][p] = 0ull; a2[q][p] = 0ull; }

    #pragma unroll
    for (int c = 0; c < NCH; c++){
        ulonglong2 hv0 = *reinterpret_cast<const ulonglong2*>(h0 + 4*c);
        ulonglong2 hv1 = *reinterpret_cast<const ulonglong2*>(h1 + 4*c);
        ulonglong2 hv2 = *reinterpret_cast<const ulonglong2*>(h2 + 4*c);
        ulonglong2 hv3 = *reinterpret_cast<const ulonglong2*>(h3 + 4*c);
        #pragma unroll
        for (int p = 0; p < NP; p++){
            ulonglong2 w1 = *reinterpret_cast<const ulonglong2*>(Wt + G1*GW + p*LG*KP + 4*c);
            ulonglong2 w2 = *reinterpret_cast<const ulonglong2*>(Wt + G2*GW + p*LG*KP + 4*c);
            fma2(a1[0][p], w1.x, hv0.x); fma2(a1[0][p], w1.y, hv0.y);
            fma2(a1[1][p], w1.x, hv1.x); fma2(a1[1][p], w1.y, hv1.y);
            fma2(a1[2][p], w1.x, hv2.x); fma2(a1[2][p], w1.y, hv2.y);
            fma2(a1[3][p], w1.x, hv3.x); fma2(a1[3][p], w1.y, hv3.y);
            fma2(a2[0][p], w2.x, hv0.x); fma2(a2[0][p], w2.y, hv0.y);
            fma2(a2[1][p], w2.x, hv1.x); fma2(a2[1][p], w2.y, hv1.y);
            fma2(a2[2][p], w2.x, hv2.x); fma2(a2[2][p], w2.y, hv2.y);
            fma2(a2[3][p], w2.x, hv3.x); fma2(a2[3][p], w2.y, hv3.y);
        }
    }

    #pragma unroll
    for (int p = 0; p < NP; p++){
        float b1v = bt[G1*HP + p*LG];
        float b2v = bt[G2*HP + p*LG];
        float w1v = 0.f, w2v = 0.f;
        if constexpr (WX){ w1v = wxt[G1*HP + p*LG]; w2v = wxt[G2*HP + p*LG]; }
        #pragma unroll
        for (int q = 0; q < NB; q++){
            float s1 = sum2(a1[q][p]) + b1v;
            float s2 = sum2(a2[q][p]) + b2v;
            if constexpr (WX){ s1 += w1v * xv[q]; s2 += w2v * xv[q]; }
            o1[q][p] = s1;
            o2[q][p] = s2;
        }
    }
}

__global__ void __launch_bounds__(TPB, 1)
lstm_pred_kernel(
    const float* __restrict__ x,
    const float* __restrict__ Wih1, const float* __restrict__ Whh1,
    const float* __restrict__ bih1, const float* __restrict__ bhh1,
    const float* __restrict__ Wih2, const float* __restrict__ Whh2,
    const float* __restrict__ bih2, const float* __restrict__ bhh2,
    const float* __restrict__ Wout, const float* __restrict__ bout,
    float* __restrict__ out)
{
    extern __shared__ float sm[];
    float* W1s   = sm;                       // [4][HP][KP]
    float* W2s   = W1s + 4*GW;               // [4][HP][KP]  (Wih2 + Whh2 combined)
    float* hS    = W2s + 4*GW;               // [BPC][HS]
    float* b1s   = hS  + BPC*HS;             // [4*HP]
    float* b2s   = b1s + 4*HP;               // [4*HP]
    float* wx1s  = b2s + 4*HP;               // [4*HP]
    float* wouts = wx1s + 4*HP;              // [HP]

    int tid = threadIdx.x;
    for (int idx = tid; idx < 4*GW; idx += TPB){
        int g   = idx / GW;
        int rem = idx - g*GW;
        int r   = rem / KP;
        int k   = rem - r*KP;
        float w1 = 0.f, w2 = 0.f;
        if (r < Hh && k < Hh){
            int src = (g*Hh + r)*Hh + k;
            w1 = Whh1[src];
            w2 = Wih2[src] + Whh2[src];
        }
        W1s[idx] = w1;
        W2s[idx] = w2;
    }
    for (int idx = tid; idx < BPC*HS; idx += TPB) hS[idx] = 0.f;
    for (int idx = tid; idx < 4*HP; idx += TPB){
        int g = idx / HP, r = idx - g*HP;
        bool v = (r < Hh);
        int src = g*Hh + (v ? r : 0);
        b1s[idx]  = v ? (bih1[src] + bhh1[src]) : 0.f;
        b2s[idx]  = v ? (bih2[src] + bhh2[src]) : 0.f;
        wx1s[idx] = v ? Wih1[src] : 0.f;
    }
    for (int idx = tid; idx < HP; idx += TPB)
        wouts[idx] = (idx < Hh) ? Wout[idx] : 0.f;
    __syncthreads();

    int grp = tid >> 4;          // 0..15
    int gid = tid & 15;          // 0..15
    int b0  = blockIdx.x * BPC + grp * NB;

    float* h0 = hS + (size_t)(grp*NB + 0) * HS;
    float* h1 = hS + (size_t)(grp*NB + 1) * HS;
    float* h2 = hS + (size_t)(grp*NB + 2) * HS;
    float* h3 = hS + (size_t)(grp*NB + 3) * HS;

    const float* W1t = W1s + gid*KP;
    const float* W2t = W2s + gid*KP;
    const float* b1t = b1s + gid;
    const float* b2t = b2s + gid;
    const float* wxt = wx1s + gid;

    float wv[NP];
    #pragma unroll
    for (int p = 0; p < NP; p++) wv[p] = wouts[gid + LG*p];

    float c1[NB][NP];
    #pragma unroll
    for (int q = 0; q < NB; q++)
        #pragma unroll
        for (int p = 0; p < NP; p++) c1[q][p] = 0.f;

    const float* xp[NB];
    float* op[NB];
    float prev[NB], xn[NB];
    #pragma unroll
    for (int q = 0; q < NB; q++){
        xp[q]   = x   + (size_t)(b0 + q) * Tt;
        op[q]   = out + (size_t)(b0 + q) * OTot;
        prev[q] = 0.f;
        xn[q]   = __ldg(xp[q]);
    }
    float bo = *bout;

    for (int t = 0; t < OTot; t++){
        float xv[NB];
        #pragma unroll
        for (int q = 0; q < NB; q++){
            xv[q] = (t < Tt) ? xn[q] : prev[q];
            if (t + 1 < Tt) xn[q] = __ldg(xp[q] + t + 1);
        }

        float a1[NB][NP], a2[NB][NP];
        float prod[NB][NP];

        // ---- layer 1: pass (i, g) then (f, o) ----
        gate_pass<0,2,true>(W1t, b1t, wxt, h0, h1, h2, h3, xv, a1, a2);
        #pragma unroll
        for (int q = 0; q < NB; q++)
            #pragma unroll
            for (int p = 0; p < NP; p++)
                prod[q][p] = sigm(a1[q][p]) * tanh_f(a2[q][p]);

        gate_pass<1,3,true>(W1t, b1t, wxt, h0, h1, h2, h3, xv, a1, a2);
        float hn[NB][NP];
        #pragma unroll
        for (int q = 0; q < NB; q++)
            #pragma unroll
            for (int p = 0; p < NP; p++){
                float cn = sigm(a1[q][p]) * c1[q][p] + prod[q][p];
                c1[q][p] = cn;
                hn[q][p] = sigm(a2[q][p]) * tanh_f(cn);
            }

        __syncwarp();
        #pragma unroll
        for (int p = 0; p < NP; p++){
            int j = gid + LG*p;          // 0..63, within HS
            h0[j] = hn[0][p];
            h1[j] = hn[1][p];
            h2[j] = hn[2][p];
            h3[j] = hn[3][p];
        }
        __syncwarp();

        // ---- layer 2 (emit): x = h = new h1, c = new c1; combined W2 ----
        gate_pass<0,2,false>(W2t, b2t, nullptr, h0, h1, h2, h3, xv, a1, a2);
        #pragma unroll
        for (int q = 0; q < NB; q++)
            #pragma unroll
            for (int p = 0; p < NP; p++)
                prod[q][p] = sigm(a1[q][p]) * tanh_f(a2[q][p]);

        gate_pass<1,3,false>(W2t, b2t, nullptr, h0, h1, h2, h3, xv, a1, a2);
        float ps[NB];
        #pragma unroll
        for (int q = 0; q < NB; q++) ps[q] = 0.f;
        #pragma unroll
        for (int q = 0; q < NB; q++)
            #pragma unroll
            for (int p = 0; p < NP; p++){
                float c2 = sigm(a1[q][p]) * c1[q][p] + prod[q][p];
                ps[q] += (sigm(a2[q][p]) * tanh_f(c2)) * wv[p];
            }

        #pragma unroll
        for (int m = 8; m; m >>= 1){
            #pragma unroll
            for (int q = 0; q < NB; q++)
                ps[q] += __shfl_xor_sync(0xffffffffu, ps[q], m, LG);
        }
        #pragma unroll
        for (int q = 0; q < NB; q++){
            float ov = ps[q] + bo;
            if (gid == 0) op[q][t] = ov;
            prev[q] = ov;
        }
    }
}

extern "C" void kernel_launch(void* const* d_in, const int* in_sizes, int n_in,
                              void* d_out, int out_size)
{
    const float* x    = (const float*)d_in[0];
    const float* Wih1 = (const float*)d_in[1];
    const float* Whh1 = (const float*)d_in[2];
    const float* bih1 = (const float*)d_in[3];
    const float* bhh1 = (const float*)d_in[4];
    const float* Wih2 = (const float*)d_in[5];
    const float* Whh2 = (const float*)d_in[6];
    const float* bih2 = (const float*)d_in[7];
    const float* bhh2 = (const float*)d_in[8];
    const float* Wout = (const float*)d_in[9];
    const float* bout = (const float*)d_in[10];
    float* out = (float*)d_out;

    const int smem_bytes = (8*GW + BPC*HS + 3*4*HP + HP) * (int)sizeof(float); // ~123 KB
    cudaFuncSetAttribute(lstm_pred_kernel,
                         cudaFuncAttributeMaxDynamicSharedMemorySize, smem_bytes);

    lstm_pred_kernel<<<Bt / BPC, TPB, smem_bytes>>>(
        x, Wih1, Whh1, bih1, bhh1, Wih2, Whh2, bih2, bhh2, Wout, bout, out);
}

// round 6
// speedup vs baseline: 1.2244x; 1.2244x over previous
#include <cuda_runtime.h>

#define Hh   51
#define H4   204
#define KP   52          // padded K dim (13 * float4)
#define NCH  13
#define Tt   2048
#define OTot 2112
#define Bt   8192
#define GRID 148         // one CTA per SM, balanced pair distribution
#define NPMAX 28         // max batch-pairs per CTA (ceil(4096/148))
#define TPB  224         // NPMAX groups * 8 lanes
#define NPOS 7

typedef unsigned long long u64;

__device__ __forceinline__ void fma2(u64 &d, u64 a, u64 b){
    asm("fma.rn.f32x2 %0, %1, %2, %0;" : "+l"(d) : "l"(a), "l"(b));
}
__device__ __forceinline__ float sum2(u64 v){
    float a, b;
    asm("mov.b64 {%0,%1}, %2;" : "=f"(a), "=f"(b) : "l"(v));
    return a + b;
}
__device__ __forceinline__ float sigm(float x){
    return __fdividef(1.0f, 1.0f + __expf(-x));
}
__device__ __forceinline__ float tanh_f(float x){
    float ax = fabsf(x);
    float e  = __expf(-2.0f * ax);
    float r  = __fdividef(1.0f - e, 1.0f + e);
    return copysignf(r, x);
}

// One K-pass for TWO gates (base pointers Wg1, Wg2) x 2 batches x NPOS rows.
template<bool WITH_X>
__device__ __forceinline__ void gate_pass(
    const float* __restrict__ Wg1, const float* __restrict__ Wg2,
    const float* __restrict__ bg1, const float* __restrict__ bg2,
    const float* __restrict__ wx1, const float* __restrict__ wx2,
    const float* __restrict__ hA,  const float* __restrict__ hB,
    const int* __restrict__ offs,  const int* __restrict__ jj,
    float xA, float xB,
    float* __restrict__ oA1, float* __restrict__ oB1,
    float* __restrict__ oA2, float* __restrict__ oB2)
{
    u64 accA1[NPOS], accB1[NPOS], accA2[NPOS], accB2[NPOS];
    #pragma unroll
    for (int p = 0; p < NPOS; p++){ accA1[p]=0ull; accB1[p]=0ull; accA2[p]=0ull; accB2[p]=0ull; }

    #pragma unroll
    for (int c = 0; c < NCH; c++){
        ulonglong2 hAv = *reinterpret_cast<const ulonglong2*>(hA + 4*c);
        ulonglong2 hBv = *reinterpret_cast<const ulonglong2*>(hB + 4*c);
        #pragma unroll
        for (int p = 0; p < NPOS; p++){
            ulonglong2 w1 = *reinterpret_cast<const ulonglong2*>(Wg1 + offs[p] + 4*c);
            fma2(accA1[p], w1.x, hAv.x);
            fma2(accA1[p], w1.y, hAv.y);
            fma2(accB1[p], w1.x, hBv.x);
            fma2(accB1[p], w1.y, hBv.y);
            ulonglong2 w2 = *reinterpret_cast<const ulonglong2*>(Wg2 + offs[p] + 4*c);
            fma2(accA2[p], w2.x, hAv.x);
            fma2(accA2[p], w2.y, hAv.y);
            fma2(accB2[p], w2.x, hBv.x);
            fma2(accB2[p], w2.y, hBv.y);
        }
    }

    #pragma unroll
    for (int p = 0; p < NPOS; p++){
        float b1v = bg1[jj[p]], b2v = bg2[jj[p]];
        float sA1 = sum2(accA1[p]) + b1v;
        float sB1 = sum2(accB1[p]) + b1v;
        float sA2 = sum2(accA2[p]) + b2v;
        float sB2 = sum2(accB2[p]) + b2v;
        if constexpr (WITH_X){
            float w1v = wx1[jj[p]], w2v = wx2[jj[p]];
            sA1 += w1v * xA;  sB1 += w1v * xB;
            sA2 += w2v * xA;  sB2 += w2v * xB;
        }
        oA1[p] = sA1; oB1[p] = sB1; oA2[p] = sA2; oB2[p] = sB2;
    }
}

__global__ void __launch_bounds__(TPB, 1)
lstm_pred_kernel(
    const float* __restrict__ x,
    const float* __restrict__ Wih1, const float* __restrict__ Whh1,
    const float* __restrict__ bih1, const float* __restrict__ bhh1,
    const float* __restrict__ Wih2, const float* __restrict__ Whh2,
    const float* __restrict__ bih2, const float* __restrict__ bhh2,
    const float* __restrict__ Wout, const float* __restrict__ bout,
    float* __restrict__ out)
{
    extern __shared__ float sm[];
    float* W1s  = sm;                        // [H4][KP]
    float* W2s  = W1s + H4*KP;               // [H4][KP]  (Wih2 + Whh2 combined)
    float* hS   = W2s + H4*KP;               // [2*NPMAX][KP]
    float* b1s  = hS  + 2*NPMAX*KP;          // [H4]
    float* b2s  = b1s + H4;                  // [H4]
    float* wx1s = b2s + H4;                  // [H4]

    int tid = threadIdx.x;
    for (int idx = tid; idx < H4*KP; idx += TPB){
        int r = idx / KP, k = idx - r*KP;
        float w1 = 0.f, w2 = 0.f;
        if (k < Hh){
            w1 = Whh1[r*Hh + k];
            w2 = Wih2[r*Hh + k] + Whh2[r*Hh + k];
        }
        W1s[idx] = w1;
        W2s[idx] = w2;
    }
    for (int idx = tid; idx < 2*NPMAX*KP; idx += TPB) hS[idx] = 0.f;
    for (int idx = tid; idx < H4; idx += TPB){
        b1s[idx]  = bih1[idx] + bhh1[idx];
        b2s[idx]  = bih2[idx] + bhh2[idx];
        wx1s[idx] = Wih1[idx];
    }
    __syncthreads();

    int grp = tid >> 3, gid = tid & 7;       // grp 0..27

    // Balanced pair distribution: CTA b owns pairs [b*4096/148, (b+1)*4096/148)
    int pair_start = (int)(((long long)blockIdx.x       * (Bt/2)) / GRID);
    int pair_end   = (int)(((long long)(blockIdx.x + 1) * (Bt/2)) / GRID);
    bool active    = grp < (pair_end - pair_start);
    int myPair     = pair_start + (active ? grp : 0);
    int bA = 2*myPair, bB = bA + 1;

    float* hA = hS + (2*grp) * KP;           // private slots even when inactive
    float* hB = hA + KP;

    int jj[NPOS], offs[NPOS];
    bool valp[NPOS];
    float woutp[NPOS];
    #pragma unroll
    for (int p = 0; p < NPOS; p++){
        int j = gid + 8*p;
        bool v = (j < Hh);
        valp[p]  = v;
        int jc   = v ? j : (Hh - 1);
        jj[p]    = jc;
        offs[p]  = jc * KP;
        woutp[p] = v ? Wout[j] : 0.f;
    }

    float cA[NPOS], cB[NPOS];
    #pragma unroll
    for (int p = 0; p < NPOS; p++){ cA[p] = 0.f; cB[p] = 0.f; }

    const float* xAp = x + (size_t)bA * Tt;
    const float* xBp = x + (size_t)bB * Tt;
    float* oAp = out + (size_t)bA * OTot;
    float* oBp = out + (size_t)bB * OTot;
    float bo = *bout;
    float prevA = 0.f, prevB = 0.f;
    float xnA = __ldg(xAp), xnB = __ldg(xBp);

    // gate order in W blocks: i, f, g, o — pair (i,g) then (f,o)
    const float* W1_i = W1s;              const float* W1_f = W1s + Hh*KP;
    const float* W1_g = W1s + 2*Hh*KP;    const float* W1_o = W1s + 3*Hh*KP;
    const float* W2_i = W2s;              const float* W2_f = W2s + Hh*KP;
    const float* W2_g = W2s + 2*Hh*KP;    const float* W2_o = W2s + 3*Hh*KP;

    for (int t = 0; t < OTot; t++){
        float xA = (t < Tt) ? xnA : prevA;
        float xB = (t < Tt) ? xnB : prevB;
        if (t + 1 < Tt){ xnA = __ldg(xAp + t + 1); xnB = __ldg(xBp + t + 1); }

        float a1A[NPOS], a1B[NPOS], a2A[NPOS], a2B[NPOS];
        float prodA[NPOS], prodB[NPOS];

        // ---- layer 1: pass (i, g) ----
        gate_pass<true>(W1_i, W1_g, b1s, b1s + 2*Hh, wx1s, wx1s + 2*Hh,
                        hA, hB, offs, jj, xA, xB, a1A, a1B, a2A, a2B);
        #pragma unroll
        for (int p = 0; p < NPOS; p++){
            prodA[p] = sigm(a1A[p]) * tanh_f(a2A[p]);
            prodB[p] = sigm(a1B[p]) * tanh_f(a2B[p]);
        }

        // ---- layer 1: pass (f, o) ----
        gate_pass<true>(W1_f, W1_o, b1s + Hh, b1s + 3*Hh, wx1s + Hh, wx1s + 3*Hh,
                        hA, hB, offs, jj, xA, xB, a1A, a1B, a2A, a2B);
        float hnA[NPOS], hnB[NPOS];
        #pragma unroll
        for (int p = 0; p < NPOS; p++){
            float cnA = sigm(a1A[p]) * cA[p] + prodA[p];
            cA[p] = cnA;
            hnA[p] = sigm(a2A[p]) * tanh_f(cnA);
            float cnB = sigm(a1B[p]) * cB[p] + prodB[p];
            cB[p] = cnB;
            hnB[p] = sigm(a2B[p]) * tanh_f(cnB);
        }
        __syncwarp();
        #pragma unroll
        for (int p = 0; p < NPOS; p++){
            if (valp[p]){ hA[jj[p]] = hnA[p]; hB[jj[p]] = hnB[p]; }
        }
        __syncwarp();

        // ---- layer 2 (emit): pass (i, g) ----
        gate_pass<false>(W2_i, W2_g, b2s, b2s + 2*Hh, nullptr, nullptr,
                         hA, hB, offs, jj, 0.f, 0.f, a1A, a1B, a2A, a2B);
        #pragma unroll
        for (int p = 0; p < NPOS; p++){
            prodA[p] = sigm(a1A[p]) * tanh_f(a2A[p]);
            prodB[p] = sigm(a1B[p]) * tanh_f(a2B[p]);
        }

        // ---- layer 2 (emit): pass (f, o) + projection ----
        gate_pass<false>(W2_f, W2_o, b2s + Hh, b2s + 3*Hh, nullptr, nullptr,
                         hA, hB, offs, jj, 0.f, 0.f, a1A, a1B, a2A, a2B);
        float pA = 0.f, pB = 0.f;
        #pragma unroll
        for (int p = 0; p < NPOS; p++){
            float c2A = sigm(a1A[p]) * cA[p] + prodA[p];
            pA += (sigm(a2A[p]) * tanh_f(c2A)) * woutp[p];
            float c2B = sigm(a1B[p]) * cB[p] + prodB[p];
            pB += (sigm(a2B[p]) * tanh_f(c2B)) * woutp[p];
        }
        #pragma unroll
        for (int m = 4; m; m >>= 1){
            pA += __shfl_xor_sync(0xffffffffu, pA, m, 8);
            pB += __shfl_xor_sync(0xffffffffu, pB, m, 8);
        }
        float ovA = pA + bo, ovB = pB + bo;
        if (gid == 0 && active){ oAp[t] = ovA; oBp[t] = ovB; }
        prevA = ovA;
        prevB = ovB;
    }
}

extern "C" void kernel_launch(void* const* d_in, const int* in_sizes, int n_in,
                              void* d_out, int out_size)
{
    const float* x    = (const float*)d_in[0];
    const float* Wih1 = (const float*)d_in[1];
    const float* Whh1 = (const float*)d_in[2];
    const float* bih1 = (const float*)d_in[3];
    const float* bhh1 = (const float*)d_in[4];
    const float* Wih2 = (const float*)d_in[5];
    const float* Whh2 = (const float*)d_in[6];
    const float* bih2 = (const float*)d_in[7];
    const float* bhh2 = (const float*)d_in[8];
    const float* Wout = (const float*)d_in[9];
    const float* bout = (const float*)d_in[10];
    float* out = (float*)d_out;

    const int smem_bytes = (2*H4*KP + 2*NPMAX*KP + 3*H4) * (int)sizeof(float); // ~99 KB
    cudaFuncSetAttribute(lstm_pred_kernel,
                         cudaFuncAttributeMaxDynamicSharedMemorySize, smem_bytes);

    lstm_pred_kernel<<<GRID, TPB, smem_bytes>>>(
        x, Wih1, Whh1, bih1, bhh1, Wih2, Whh2, bih2, bhh2, Wout, bout, out);
}